// round 12
// baseline (speedup 1.0000x reference)
#include <cuda_runtime.h>
#include <cstdint>

// Problem constants
#define BB   2
#define SS_  2048
#define DIM_ 1024
#define HH   16
#define DH_  64
#define MM   (BB * SS_)     // 4096
#define HD_  (HH * DH_)     // 1024

// Scratch (device globals: allocation-free rule)
__device__ float g_Q[BB * HH * SS_ * DH_];   // [B,H,S,DH]
__device__ float g_K[BB * HH * SS_ * DH_];
__device__ float g_V[BB * HH * SS_ * DH_];
__device__ float g_C[MM * HD_];              // ctx, [B,S,H*DH] row-major

// ---------------------------------------------------------------------------
// Helpers
// ---------------------------------------------------------------------------
__device__ __forceinline__ uint32_t f2tf32(float x) {
    uint32_t u;
    asm("cvt.rna.tf32.f32 %0, %1;" : "=r"(u) : "f"(x));
    return u;
}

// D = A(16x8 tf32) * B(8x8 tf32) + D, fp32 accumulate
__device__ __forceinline__ void mma_tf32(float* c, const uint32_t* a, const uint32_t* b) {
    asm volatile(
        "mma.sync.aligned.m16n8k8.row.col.f32.tf32.tf32.f32 "
        "{%0,%1,%2,%3}, {%4,%5,%6,%7}, {%8,%9}, {%0,%1,%2,%3};"
        : "+f"(c[0]), "+f"(c[1]), "+f"(c[2]), "+f"(c[3])
        : "r"(a[0]), "r"(a[1]), "r"(a[2]), "r"(a[3]), "r"(b[0]), "r"(b[1]));
}

// ===========================================================================
// tf32 mma.sync GEMM, software-pipelined (double-buffered SMEM + reg staging)
//   C[M,N] = A[M,1024] @ W[1024,N] + bias
//   CTA tile 128x128, 8 warps of 64x32, K-chunk 32.
//   MODE 0: qkv (blockIdx.z selects W/bias; scatter into g_Q/g_K/g_V)
//   MODE 1: out projection (A = g_C, W = W0 = Wo, bias = b0 = bo)
// ===========================================================================
#define GAS 36    // As stride (u32)
#define GBS 132   // Bs stride (u32)
#define GEMM_ABUF (128 * GAS)             // 4608 u32
#define GEMM_BBUF (32 * GBS)              // 4224 u32
#define GEMM_SMEM_U32 (2 * (GEMM_ABUF + GEMM_BBUF))
#define GEMM_SMEM_BYTES (GEMM_SMEM_U32 * 4)   // 70656

__device__ __forceinline__ void gemm_ldg(const float* __restrict__ A,
                                         const float* __restrict__ W,
                                         int m0, int n0, int k0, int tid,
                                         float4* ra, float4* rb) {
#pragma unroll
    for (int t = 0; t < 4; t++) {
        int idx = tid + t * 256;
        int r = idx >> 3;
        int c4 = (idx & 7) * 4;
        ra[t] = *(const float4*)(A + (size_t)(m0 + r) * DIM_ + k0 + c4);
    }
#pragma unroll
    for (int t = 0; t < 4; t++) {
        int idx = tid + t * 256;
        int kk = idx >> 5;
        int n4 = (idx & 31) * 4;
        rb[t] = *(const float4*)(W + (size_t)(k0 + kk) * HD_ + n0 + n4);
    }
}

__device__ __forceinline__ void gemm_sts(uint32_t* As, uint32_t* Bs, int tid,
                                         const float4* ra, const float4* rb) {
#pragma unroll
    for (int t = 0; t < 4; t++) {
        int idx = tid + t * 256;
        int r = idx >> 3;
        int c4 = (idx & 7) * 4;
        uint32_t* p = &As[r * GAS + c4];
        p[0] = f2tf32(ra[t].x); p[1] = f2tf32(ra[t].y);
        p[2] = f2tf32(ra[t].z); p[3] = f2tf32(ra[t].w);
    }
#pragma unroll
    for (int t = 0; t < 4; t++) {
        int idx = tid + t * 256;
        int kk = idx >> 5;
        int n4 = (idx & 31) * 4;
        uint32_t* p = &Bs[kk * GBS + n4];
        p[0] = f2tf32(rb[t].x); p[1] = f2tf32(rb[t].y);
        p[2] = f2tf32(rb[t].z); p[3] = f2tf32(rb[t].w);
    }
}

template <int MODE>
__global__ __launch_bounds__(256) void gemm_mma(
    const float* __restrict__ Ain,
    const float* __restrict__ W0, const float* __restrict__ b0,
    const float* __restrict__ W1, const float* __restrict__ b1,
    const float* __restrict__ W2, const float* __restrict__ b2,
    float* __restrict__ outp)
{
    extern __shared__ uint32_t dsm[];
    uint32_t* Asb[2] = { dsm, dsm + GEMM_ABUF };
    uint32_t* Bsb[2] = { dsm + 2 * GEMM_ABUF, dsm + 2 * GEMM_ABUF + GEMM_BBUF };

    const int tid  = threadIdx.x;
    const int wid  = tid >> 5;
    const int lane = tid & 31;
    const int g    = lane >> 2;   // 0..7
    const int q    = lane & 3;    // 0..3
    const int m0 = blockIdx.y * 128;
    const int n0 = blockIdx.x * 128;
    const int wm = (wid >> 2) * 64;   // warp m-offset (0 or 64)
    const int wn = (wid & 3) * 32;    // warp n-offset (0,32,64,96)

    const float* A;
    const float* W;
    const float* bias;
    float* op;
    if (MODE == 0) {
        A = Ain;
        int z = blockIdx.z;
        W    = (z == 0) ? W0 : (z == 1) ? W1 : W2;
        bias = (z == 0) ? b0 : (z == 1) ? b1 : b2;
        op   = nullptr;
    } else {
        A = g_C; W = W0; bias = b0; op = outp;
    }

    float acc[4][4][4];
#pragma unroll
    for (int mt = 0; mt < 4; mt++)
#pragma unroll
        for (int nt = 0; nt < 4; nt++)
#pragma unroll
            for (int j = 0; j < 4; j++) acc[mt][nt][j] = 0.0f;

    float4 ra[4], rb[4];

    // Prologue: chunk 0 -> buffer 0
    gemm_ldg(A, W, m0, n0, 0, tid, ra, rb);
    gemm_sts(Asb[0], Bsb[0], tid, ra, rb);
    __syncthreads();

#pragma unroll 1
    for (int c = 0; c < DIM_ / 32; c++) {
        const int cur = c & 1;
        // Issue next chunk's global loads before compute (latency overlap)
        if (c + 1 < DIM_ / 32)
            gemm_ldg(A, W, m0, n0, (c + 1) * 32, tid, ra, rb);

        const uint32_t* As = Asb[cur];
        const uint32_t* Bs = Bsb[cur];
#pragma unroll
        for (int ks = 0; ks < 32; ks += 8) {
            uint32_t a[4][4], bfr[4][2];
#pragma unroll
            for (int mt = 0; mt < 4; mt++) {
                int r = wm + mt * 16 + g;
                a[mt][0] = As[r * GAS + ks + q];
                a[mt][1] = As[(r + 8) * GAS + ks + q];
                a[mt][2] = As[r * GAS + ks + q + 4];
                a[mt][3] = As[(r + 8) * GAS + ks + q + 4];
            }
#pragma unroll
            for (int nt = 0; nt < 4; nt++) {
                int n = wn + nt * 8 + g;
                bfr[nt][0] = Bs[(ks + q) * GBS + n];
                bfr[nt][1] = Bs[(ks + q + 4) * GBS + n];
            }
#pragma unroll
            for (int mt = 0; mt < 4; mt++)
#pragma unroll
                for (int nt = 0; nt < 4; nt++)
                    mma_tf32(acc[mt][nt], a[mt], bfr[nt]);
        }

        if (c + 1 < DIM_ / 32)
            gemm_sts(Asb[cur ^ 1], Bsb[cur ^ 1], tid, ra, rb);
        __syncthreads();
    }

    // Epilogue: C frag (rows g,g+8 ; cols 2q,2q+1) + bias, scatter/store
#pragma unroll
    for (int mt = 0; mt < 4; mt++) {
#pragma unroll
        for (int nt = 0; nt < 4; nt++) {
            int n = n0 + wn + nt * 8 + 2 * q;
            float bn0 = bias[n], bn1 = bias[n + 1];
            int mA = m0 + wm + mt * 16 + g;
            int mB = mA + 8;
            float2 v0 = make_float2(acc[mt][nt][0] + bn0, acc[mt][nt][1] + bn1);
            float2 v1 = make_float2(acc[mt][nt][2] + bn0, acc[mt][nt][3] + bn1);
            if (MODE == 0) {
                float* dst = (blockIdx.z == 0) ? g_Q : (blockIdx.z == 1) ? g_K : g_V;
                int h = n >> 6, d = n & 63;
                int bA = mA >> 11, sA = mA & 2047;
                int bW = mB >> 11, sB = mB & 2047;
                *(float2*)(dst + ((((size_t)(bA * HH + h)) * SS_ + sA) << 6) + d) = v0;
                *(float2*)(dst + ((((size_t)(bW * HH + h)) * SS_ + sB) << 6) + d) = v1;
            } else {
                *(float2*)(op + (size_t)mA * DIM_ + n) = v0;
                *(float2*)(op + (size_t)mB * DIM_ + n) = v1;
            }
        }
    }
}

// ===========================================================================
// Flash attention with tf32 mma.sync, K/V double-buffered + reg-staged
//   q-tile 128 per CTA, 8 warps x 16 q-rows, key-tile 64, DH=64.
//   Per warp: S = 16x64 (8 n-subtiles), O = 16x64. P is warp-private in SMEM.
// ===========================================================================
#define AQS 68
#define AKS 68
#define AVS 68
#define APS 68
#define AT_QOFF 0
#define AT_KOFF (128 * AQS)                    // K buffers: 2 x 64*AKS
#define AT_VOFF (AT_KOFF + 2 * 64 * AKS)       // V buffers: 2 x 64*AVS
#define AT_POFF (AT_VOFF + 2 * 64 * AVS)
#define AT_MOFF (AT_POFF + 128 * APS)          // mask: 2 x 64 floats
#define ATTN_SMEM_U32 (AT_MOFF + 128)
#define ATTN_SMEM_BYTES (ATTN_SMEM_U32 * 4)    // 139776

__global__ __launch_bounds__(256) void attn_mma(const float* __restrict__ mask)
{
    extern __shared__ uint32_t sm[];
    uint32_t* Qs = sm + AT_QOFF;
    uint32_t* Ksb[2] = { sm + AT_KOFF, sm + AT_KOFF + 64 * AKS };
    uint32_t* Vsb[2] = { sm + AT_VOFF, sm + AT_VOFF + 64 * AVS };
    uint32_t* Ps = sm + AT_POFF;
    float*   mskb[2] = { (float*)(sm + AT_MOFF), (float*)(sm + AT_MOFF + 64) };

    const int tid  = threadIdx.x;
    const int wid  = tid >> 5;
    const int lane = tid & 31;
    const int g    = lane >> 2;
    const int q    = lane & 3;
    const int bh = blockIdx.y;
    const int b  = bh >> 4;
    const int h  = bh & 15;
    const int q0 = blockIdx.x * 128;
    const int wq = wid * 16;

    const float* Qg = g_Q + (size_t)bh * SS_ * DH_;
    const float* Kg = g_K + (size_t)bh * SS_ * DH_;
    const float* Vg = g_V + (size_t)bh * SS_ * DH_;

    // Load Q tile (128 x 64), fold 1/sqrt(DH)=0.125
#pragma unroll
    for (int t = 0; t < 8; t++) {
        int idx = tid + t * 256;
        int r = idx >> 4;
        int c4 = (idx & 15) * 4;
        float4 v = *(const float4*)(Qg + (size_t)(q0 + r) * DH_ + c4);
        uint32_t* p = &Qs[r * AQS + c4];
        p[0] = f2tf32(v.x * 0.125f); p[1] = f2tf32(v.y * 0.125f);
        p[2] = f2tf32(v.z * 0.125f); p[3] = f2tf32(v.w * 0.125f);
    }

    float O[8][4];
#pragma unroll
    for (int nt = 0; nt < 8; nt++)
#pragma unroll
        for (int j = 0; j < 4; j++) O[nt][j] = 0.0f;
    float m0r = -1e30f, m1r = -1e30f, l0 = 0.0f, l1 = 0.0f;

    float4 rk[4], rv[4];
    float  rm = 1.0f;

    // Prologue: tile 0 -> buffer 0
#pragma unroll
    for (int t = 0; t < 4; t++) {
        int idx = tid + t * 256;
        int r = idx >> 4;
        int c4 = (idx & 15) * 4;
        rk[t] = *(const float4*)(Kg + (size_t)r * DH_ + c4);
        rv[t] = *(const float4*)(Vg + (size_t)r * DH_ + c4);
    }
    if (tid < 64) rm = mask[b * SS_ + tid];
#pragma unroll
    for (int t = 0; t < 4; t++) {
        int idx = tid + t * 256;
        int r = idx >> 4;
        int c4 = (idx & 15) * 4;
        uint32_t* pk = &Ksb[0][r * AKS + c4];
        pk[0] = f2tf32(rk[t].x); pk[1] = f2tf32(rk[t].y);
        pk[2] = f2tf32(rk[t].z); pk[3] = f2tf32(rk[t].w);
        uint32_t* pv = &Vsb[0][r * AVS + c4];
        pv[0] = f2tf32(rv[t].x); pv[1] = f2tf32(rv[t].y);
        pv[2] = f2tf32(rv[t].z); pv[3] = f2tf32(rv[t].w);
    }
    if (tid < 64) mskb[0][tid] = rm;
    __syncthreads();

#pragma unroll 1
    for (int kt = 0; kt < SS_ / 64; kt++) {
        const int cur = kt & 1;
        const uint32_t* Ks = Ksb[cur];
        const uint32_t* Vs = Vsb[cur];
        const float*   msk = mskb[cur];

        // Issue next tile's global loads early
        if (kt + 1 < SS_ / 64) {
            int k0n = (kt + 1) * 64;
#pragma unroll
            for (int t = 0; t < 4; t++) {
                int idx = tid + t * 256;
                int r = idx >> 4;
                int c4 = (idx & 15) * 4;
                rk[t] = *(const float4*)(Kg + (size_t)(k0n + r) * DH_ + c4);
                rv[t] = *(const float4*)(Vg + (size_t)(k0n + r) * DH_ + c4);
            }
            if (tid < 64) rm = mask[b * SS_ + k0n + tid];
        }

        // S = Q @ K^T  (per-warp 16 x 64)
        float s[8][4];
#pragma unroll
        for (int nt = 0; nt < 8; nt++)
#pragma unroll
            for (int j = 0; j < 4; j++) s[nt][j] = 0.0f;

#pragma unroll
        for (int ks = 0; ks < 64; ks += 8) {
            uint32_t a[4];
            a[0] = Qs[(wq + g) * AQS + ks + q];
            a[1] = Qs[(wq + g + 8) * AQS + ks + q];
            a[2] = Qs[(wq + g) * AQS + ks + q + 4];
            a[3] = Qs[(wq + g + 8) * AQS + ks + q + 4];
#pragma unroll
            for (int nt = 0; nt < 8; nt++) {
                uint32_t bb[2];
                bb[0] = Ks[(nt * 8 + g) * AKS + ks + q];
                bb[1] = Ks[(nt * 8 + g) * AKS + ks + q + 4];
                mma_tf32(s[nt], a, bb);
            }
        }

        // Mask + row max (rows g and g+8; this warp owns the full 64-key width)
        float mx0 = -1e30f, mx1 = -1e30f;
#pragma unroll
        for (int nt = 0; nt < 8; nt++) {
            int col = nt * 8 + 2 * q;
            float mk0 = 1.0e6f * (1.0f - msk[col]);
            float mk1 = 1.0e6f * (1.0f - msk[col + 1]);
            s[nt][0] -= mk0; s[nt][1] -= mk1;
            s[nt][2] -= mk0; s[nt][3] -= mk1;
            mx0 = fmaxf(mx0, fmaxf(s[nt][0], s[nt][1]));
            mx1 = fmaxf(mx1, fmaxf(s[nt][2], s[nt][3]));
        }
        mx0 = fmaxf(mx0, __shfl_xor_sync(0xffffffffu, mx0, 1));
        mx0 = fmaxf(mx0, __shfl_xor_sync(0xffffffffu, mx0, 2));
        mx1 = fmaxf(mx1, __shfl_xor_sync(0xffffffffu, mx1, 1));
        mx1 = fmaxf(mx1, __shfl_xor_sync(0xffffffffu, mx1, 2));

        float mn0 = fmaxf(m0r, mx0), mn1 = fmaxf(m1r, mx1);
        float c0 = __expf(m0r - mn0), c1 = __expf(m1r - mn1);
        m0r = mn0; m1r = mn1;

        float s0 = 0.0f, s1 = 0.0f;
#pragma unroll
        for (int nt = 0; nt < 8; nt++) {
            float p0 = __expf(s[nt][0] - mn0);
            float p1 = __expf(s[nt][1] - mn0);
            float p2 = __expf(s[nt][2] - mn1);
            float p3 = __expf(s[nt][3] - mn1);
            s0 += p0 + p1; s1 += p2 + p3;
            int col = nt * 8 + 2 * q;
            Ps[(wq + g) * APS + col]     = f2tf32(p0);
            Ps[(wq + g) * APS + col + 1] = f2tf32(p1);
            Ps[(wq + g + 8) * APS + col]     = f2tf32(p2);
            Ps[(wq + g + 8) * APS + col + 1] = f2tf32(p3);
            O[nt][0] *= c0; O[nt][1] *= c0;
            O[nt][2] *= c1; O[nt][3] *= c1;
        }
        s0 += __shfl_xor_sync(0xffffffffu, s0, 1);
        s0 += __shfl_xor_sync(0xffffffffu, s0, 2);
        s1 += __shfl_xor_sync(0xffffffffu, s1, 1);
        s1 += __shfl_xor_sync(0xffffffffu, s1, 2);
        l0 = l0 * c0 + s0;
        l1 = l1 * c1 + s1;

        __syncwarp();   // Ps rows [wq, wq+16) are warp-private; lane visibility only

        // O += P @ V  (k = key dim 64)
#pragma unroll
        for (int ks = 0; ks < 64; ks += 8) {
            uint32_t a[4];
            a[0] = Ps[(wq + g) * APS + ks + q];
            a[1] = Ps[(wq + g + 8) * APS + ks + q];
            a[2] = Ps[(wq + g) * APS + ks + q + 4];
            a[3] = Ps[(wq + g + 8) * APS + ks + q + 4];
#pragma unroll
            for (int nt = 0; nt < 8; nt++) {
                uint32_t bb[2];
                bb[0] = Vs[(ks + q) * AVS + nt * 8 + g];
                bb[1] = Vs[(ks + q + 4) * AVS + nt * 8 + g];
                mma_tf32(O[nt], a, bb);
            }
        }

        // Store staged next tile into the alternate buffer
        if (kt + 1 < SS_ / 64) {
#pragma unroll
            for (int t = 0; t < 4; t++) {
                int idx = tid + t * 256;
                int r = idx >> 4;
                int c4 = (idx & 15) * 4;
                uint32_t* pk = &Ksb[cur ^ 1][r * AKS + c4];
                pk[0] = f2tf32(rk[t].x); pk[1] = f2tf32(rk[t].y);
                pk[2] = f2tf32(rk[t].z); pk[3] = f2tf32(rk[t].w);
                uint32_t* pv = &Vsb[cur ^ 1][r * AVS + c4];
                pv[0] = f2tf32(rv[t].x); pv[1] = f2tf32(rv[t].y);
                pv[2] = f2tf32(rv[t].z); pv[3] = f2tf32(rv[t].w);
            }
            if (tid < 64) mskb[cur ^ 1][tid] = rm;
        }
        __syncthreads();
    }

    // Normalize and write ctx [B,S,H*DH]
    float inv0 = 1.0f / l0, inv1 = 1.0f / l1;
    int qr0 = q0 + wq + g;
    int qr1 = qr0 + 8;
#pragma unroll
    for (int nt = 0; nt < 8; nt++) {
        int d = nt * 8 + 2 * q;
        float2 v0 = make_float2(O[nt][0] * inv0, O[nt][1] * inv0);
        float2 v1 = make_float2(O[nt][2] * inv1, O[nt][3] * inv1);
        *(float2*)(g_C + ((size_t)(b * SS_ + qr0)) * HD_ + h * 64 + d) = v0;
        *(float2*)(g_C + ((size_t)(b * SS_ + qr1)) * HD_ + h * 64 + d) = v1;
    }
}

// ===========================================================================
extern "C" void kernel_launch(void* const* d_in, const int* in_sizes, int n_in,
                              void* d_out, int out_size)
{
    const float* X    = (const float*)d_in[0];
    const float* mask = (const float*)d_in[1];
    const float* Wq   = (const float*)d_in[2];
    const float* bq   = (const float*)d_in[3];
    const float* Wk   = (const float*)d_in[4];
    const float* bk   = (const float*)d_in[5];
    const float* Wv   = (const float*)d_in[6];
    const float* bv   = (const float*)d_in[7];
    const float* Wo   = (const float*)d_in[8];
    const float* bo   = (const float*)d_in[9];
    float* out        = (float*)d_out;

    cudaFuncSetAttribute(gemm_mma<0>, cudaFuncAttributeMaxDynamicSharedMemorySize,
                         GEMM_SMEM_BYTES);
    cudaFuncSetAttribute(gemm_mma<1>, cudaFuncAttributeMaxDynamicSharedMemorySize,
                         GEMM_SMEM_BYTES);
    cudaFuncSetAttribute(attn_mma, cudaFuncAttributeMaxDynamicSharedMemorySize,
                         ATTN_SMEM_BYTES);

    gemm_mma<0><<<dim3(HD_ / 128, MM / 128, 3), 256, GEMM_SMEM_BYTES>>>(
        X, Wq, bq, Wk, bk, Wv, bv, nullptr);
    attn_mma<<<dim3(SS_ / 128, BB * HH), 256, ATTN_SMEM_BYTES>>>(mask);
    // MODE 1 reads W=W0, bias=b0 — Wo/bo go in those slots.
    gemm_mma<1><<<dim3(DIM_ / 128, MM / 128), 256, GEMM_SMEM_BYTES>>>(
        nullptr, Wo, bo, nullptr, nullptr, nullptr, nullptr, out);
}

// round 13
// speedup vs baseline: 1.9843x; 1.9843x over previous
#include <cuda_runtime.h>
#include <cstdint>

// Problem constants
#define BB   2
#define SS_  2048
#define DIM_ 1024
#define HH   16
#define DH_  64
#define MM   (BB * SS_)     // 4096
#define HD_  (HH * DH_)     // 1024

// Scratch (device globals: allocation-free rule)
__device__ float g_Q[BB * HH * SS_ * DH_];   // [B,H,S,DH]
__device__ float g_K[BB * HH * SS_ * DH_];
__device__ float g_V[BB * HH * SS_ * DH_];
__device__ float g_C[MM * HD_];              // ctx, [B,S,H*DH] row-major

// ---------------------------------------------------------------------------
// Helpers
// ---------------------------------------------------------------------------
__device__ __forceinline__ uint32_t smem_u32(const void* p) {
    uint32_t a;
    asm("{ .reg .u64 t; cvta.to.shared.u64 t, %1; cvt.u32.u64 %0, t; }"
        : "=r"(a) : "l"(p));
    return a;
}

__device__ __forceinline__ uint32_t f2tf32(float x) {
    uint32_t u;
    asm("cvt.rna.tf32.f32 %0, %1;" : "=r"(u) : "f"(x));
    return u;
}

// smem u32 word (raw fp32 bits) -> tf32 (rna) — identical numerics to cvt-at-STS
__device__ __forceinline__ uint32_t s2tf32(uint32_t raw) {
    return f2tf32(__uint_as_float(raw));
}

__device__ __forceinline__ void cp_async16(uint32_t saddr, const void* gptr) {
    asm volatile("cp.async.cg.shared.global [%0], [%1], 16;"
                 :: "r"(saddr), "l"(gptr));
}
#define CP_COMMIT() asm volatile("cp.async.commit_group;" ::: "memory")
#define CP_WAIT(n)  asm volatile("cp.async.wait_group %0;" :: "n"(n) : "memory")

// D = A(16x8 tf32) * B(8x8 tf32) + D, fp32 accumulate
__device__ __forceinline__ void mma_tf32(float* c, const uint32_t* a, const uint32_t* b) {
    asm volatile(
        "mma.sync.aligned.m16n8k8.row.col.f32.tf32.tf32.f32 "
        "{%0,%1,%2,%3}, {%4,%5,%6,%7}, {%8,%9}, {%0,%1,%2,%3};"
        : "+f"(c[0]), "+f"(c[1]), "+f"(c[2]), "+f"(c[3])
        : "r"(a[0]), "r"(a[1]), "r"(a[2]), "r"(a[3]), "r"(b[0]), "r"(b[1]));
}

// ===========================================================================
// tf32 mma.sync GEMM, cp.async double-buffered (no register staging)
//   C[M,N] = A[M,1024] @ W[1024,N] + bias
//   CTA tile 128x128, 8 warps of 64x32, K-chunk 32. SMEM holds raw fp32;
//   cvt.rna applied at fragment load (numerics identical to cvt-at-STS).
//   MODE 0: qkv (blockIdx.z selects W/bias; scatter into g_Q/g_K/g_V)
//   MODE 1: out projection (A = g_C, W = W0 = Wo, bias = b0 = bo)
// ===========================================================================
#define GAS 36    // As stride (u32)
#define GBS 132   // Bs stride (u32)
#define GEMM_ABUF (128 * GAS)             // 4608 u32
#define GEMM_BBUF (32 * GBS)              // 4224 u32
#define GEMM_SMEM_U32 (2 * (GEMM_ABUF + GEMM_BBUF))
#define GEMM_SMEM_BYTES (GEMM_SMEM_U32 * 4)   // 70656
#define NCH (DIM_ / 32)                   // 32 k-chunks

__device__ __forceinline__ void gemm_cp(uint32_t a_s, uint32_t b_s,
                                        const float* __restrict__ A,
                                        const float* __restrict__ W,
                                        int m0, int n0, int k0, int tid) {
#pragma unroll
    for (int t = 0; t < 4; t++) {
        int idx = tid + t * 256;
        int r = idx >> 3;
        int c4 = (idx & 7) << 2;
        cp_async16(a_s + (uint32_t)(r * GAS + c4) * 4,
                   A + (size_t)(m0 + r) * DIM_ + k0 + c4);
    }
#pragma unroll
    for (int t = 0; t < 4; t++) {
        int idx = tid + t * 256;
        int kk = idx >> 5;
        int n4 = (idx & 31) << 2;
        cp_async16(b_s + (uint32_t)(kk * GBS + n4) * 4,
                   W + (size_t)(k0 + kk) * HD_ + n0 + n4);
    }
}

template <int MODE>
__global__ __launch_bounds__(256) void gemm_mma(
    const float* __restrict__ Ain,
    const float* __restrict__ W0, const float* __restrict__ b0,
    const float* __restrict__ W1, const float* __restrict__ b1,
    const float* __restrict__ W2, const float* __restrict__ b2,
    float* __restrict__ outp)
{
    extern __shared__ uint32_t dsm[];
    const uint32_t sb = smem_u32(dsm);

    const int tid  = threadIdx.x;
    const int wid  = tid >> 5;
    const int lane = tid & 31;
    const int g    = lane >> 2;   // 0..7
    const int q    = lane & 3;    // 0..3
    const int m0 = blockIdx.y * 128;
    const int n0 = blockIdx.x * 128;
    const int wm = (wid >> 2) * 64;   // warp m-offset (0 or 64)
    const int wn = (wid & 3) * 32;    // warp n-offset (0,32,64,96)

    const float* A;
    const float* W;
    const float* bias;
    float* op;
    if (MODE == 0) {
        A = Ain;
        int z = blockIdx.z;
        W    = (z == 0) ? W0 : (z == 1) ? W1 : W2;
        bias = (z == 0) ? b0 : (z == 1) ? b1 : b2;
        op   = nullptr;
    } else {
        A = g_C; W = W0; bias = b0; op = outp;
    }

    float acc[4][4][4];
#pragma unroll
    for (int mt = 0; mt < 4; mt++)
#pragma unroll
        for (int nt = 0; nt < 4; nt++)
#pragma unroll
            for (int j = 0; j < 4; j++) acc[mt][nt][j] = 0.0f;

    // Prologue: chunk 0 -> buffer 0
    gemm_cp(sb, sb + 2 * GEMM_ABUF * 4, A, W, m0, n0, 0, tid);
    CP_COMMIT();

#pragma unroll 1
    for (int c = 0; c < NCH; c++) {
        const int cur = c & 1;
        if (c + 1 < NCH) {
            const int nxt = cur ^ 1;
            gemm_cp(sb + nxt * GEMM_ABUF * 4,
                    sb + (2 * GEMM_ABUF + nxt * GEMM_BBUF) * 4,
                    A, W, m0, n0, (c + 1) * 32, tid);
            CP_COMMIT();
            CP_WAIT(1);
        } else {
            CP_WAIT(0);
        }
        __syncthreads();

        const uint32_t* As = dsm + cur * GEMM_ABUF;
        const uint32_t* Bs = dsm + 2 * GEMM_ABUF + cur * GEMM_BBUF;
#pragma unroll
        for (int ks = 0; ks < 32; ks += 8) {
            uint32_t a[4][4], bfr[4][2];
#pragma unroll
            for (int mt = 0; mt < 4; mt++) {
                int r = wm + mt * 16 + g;
                a[mt][0] = s2tf32(As[r * GAS + ks + q]);
                a[mt][1] = s2tf32(As[(r + 8) * GAS + ks + q]);
                a[mt][2] = s2tf32(As[r * GAS + ks + q + 4]);
                a[mt][3] = s2tf32(As[(r + 8) * GAS + ks + q + 4]);
            }
#pragma unroll
            for (int nt = 0; nt < 4; nt++) {
                int n = wn + nt * 8 + g;
                bfr[nt][0] = s2tf32(Bs[(ks + q) * GBS + n]);
                bfr[nt][1] = s2tf32(Bs[(ks + q + 4) * GBS + n]);
            }
#pragma unroll
            for (int mt = 0; mt < 4; mt++)
#pragma unroll
                for (int nt = 0; nt < 4; nt++)
                    mma_tf32(acc[mt][nt], a[mt], bfr[nt]);
        }
        __syncthreads();   // buffer `cur` is rewritten by next iteration's cp.async
    }

    // Epilogue: C frag (rows g,g+8 ; cols 2q,2q+1) + bias, scatter/store
#pragma unroll
    for (int mt = 0; mt < 4; mt++) {
#pragma unroll
        for (int nt = 0; nt < 4; nt++) {
            int n = n0 + wn + nt * 8 + 2 * q;
            float bn0 = bias[n], bn1 = bias[n + 1];
            int mA = m0 + wm + mt * 16 + g;
            int mB = mA + 8;
            float2 v0 = make_float2(acc[mt][nt][0] + bn0, acc[mt][nt][1] + bn1);
            float2 v1 = make_float2(acc[mt][nt][2] + bn0, acc[mt][nt][3] + bn1);
            if (MODE == 0) {
                float* dst = (blockIdx.z == 0) ? g_Q : (blockIdx.z == 1) ? g_K : g_V;
                int h = n >> 6, d = n & 63;
                int bA = mA >> 11, sA = mA & 2047;
                int bW = mB >> 11, sB = mB & 2047;
                *(float2*)(dst + ((((size_t)(bA * HH + h)) * SS_ + sA) << 6) + d) = v0;
                *(float2*)(dst + ((((size_t)(bW * HH + h)) * SS_ + sB) << 6) + d) = v1;
            } else {
                *(float2*)(op + (size_t)mA * DIM_ + n) = v0;
                *(float2*)(op + (size_t)mB * DIM_ + n) = v1;
            }
        }
    }
}

// ===========================================================================
// Flash attention with tf32 mma.sync, cp.async double-buffered K/V
//   q-tile 128 per CTA, 8 warps x 16 q-rows, key-tile 64, DH=64.
//   K/V SMEM holds raw fp32; cvt.rna at fragment load. Q and P stored as tf32.
// ===========================================================================
#define AQS 68
#define AKS 68
#define AVS 68
#define APS 68
#define AT_QOFF 0
#define AT_KOFF (128 * AQS)                    // K buffers: 2 x 64*AKS (fp32)
#define AT_VOFF (AT_KOFF + 2 * 64 * AKS)       // V buffers: 2 x 64*AVS (fp32)
#define AT_POFF (AT_VOFF + 2 * 64 * AVS)
#define AT_MOFF (AT_POFF + 128 * APS)          // mask: 2 x 64 floats
#define ATTN_SMEM_U32 (AT_MOFF + 128)
#define ATTN_SMEM_BYTES (ATTN_SMEM_U32 * 4)    // 139776

__device__ __forceinline__ void attn_cp(uint32_t k_s, uint32_t v_s,
                                        const float* __restrict__ Kg,
                                        const float* __restrict__ Vg,
                                        int k0, int tid) {
#pragma unroll
    for (int t = 0; t < 2; t++) {
        int idx = tid + t * 256;
        int r = idx >> 3;            // 0..63
        int c4 = (idx & 7) << 3;     // 0,8,..56 — two 16B chunks per thread pair
        cp_async16(k_s + (uint32_t)(r * AKS + c4) * 4,
                   Kg + (size_t)(k0 + r) * DH_ + c4);
        cp_async16(k_s + (uint32_t)(r * AKS + c4 + 4) * 4,
                   Kg + (size_t)(k0 + r) * DH_ + c4 + 4);
        cp_async16(v_s + (uint32_t)(r * AVS + c4) * 4,
                   Vg + (size_t)(k0 + r) * DH_ + c4);
        cp_async16(v_s + (uint32_t)(r * AVS + c4 + 4) * 4,
                   Vg + (size_t)(k0 + r) * DH_ + c4 + 4);
    }
}

__global__ __launch_bounds__(256) void attn_mma(const float* __restrict__ mask)
{
    extern __shared__ uint32_t sm[];
    const uint32_t sb = smem_u32(sm);
    uint32_t* Qs = sm + AT_QOFF;
    uint32_t* Ps = sm + AT_POFF;

    const int tid  = threadIdx.x;
    const int wid  = tid >> 5;
    const int lane = tid & 31;
    const int g    = lane >> 2;
    const int q    = lane & 3;
    const int bh = blockIdx.y;
    const int b  = bh >> 4;
    const int h  = bh & 15;
    const int q0 = blockIdx.x * 128;
    const int wq = wid * 16;

    const float* Qg = g_Q + (size_t)bh * SS_ * DH_;
    const float* Kg = g_K + (size_t)bh * SS_ * DH_;
    const float* Vg = g_V + (size_t)bh * SS_ * DH_;

    // Prologue: tile 0 K/V via cp.async into buffer 0
    attn_cp(sb + AT_KOFF * 4, sb + AT_VOFF * 4, Kg, Vg, 0, tid);
    CP_COMMIT();

    // Load Q tile (128 x 64), fold 1/sqrt(DH)=0.125, store tf32
#pragma unroll
    for (int t = 0; t < 8; t++) {
        int idx = tid + t * 256;
        int r = idx >> 4;
        int c4 = (idx & 15) * 4;
        float4 v = *(const float4*)(Qg + (size_t)(q0 + r) * DH_ + c4);
        uint32_t* p = &Qs[r * AQS + c4];
        p[0] = f2tf32(v.x * 0.125f); p[1] = f2tf32(v.y * 0.125f);
        p[2] = f2tf32(v.z * 0.125f); p[3] = f2tf32(v.w * 0.125f);
    }
    if (tid < 64) ((float*)(sm + AT_MOFF))[tid] = mask[b * SS_ + tid];

    float O[8][4];
#pragma unroll
    for (int nt = 0; nt < 8; nt++)
#pragma unroll
        for (int j = 0; j < 4; j++) O[nt][j] = 0.0f;
    float m0r = -1e30f, m1r = -1e30f, l0 = 0.0f, l1 = 0.0f;
    float rm = 1.0f;

#pragma unroll 1
    for (int kt = 0; kt < SS_ / 64; kt++) {
        const int cur = kt & 1;
        const int nxt = cur ^ 1;

        if (kt + 1 < SS_ / 64) {
            int k0n = (kt + 1) * 64;
            attn_cp(sb + (AT_KOFF + nxt * 64 * AKS) * 4,
                    sb + (AT_VOFF + nxt * 64 * AVS) * 4,
                    Kg, Vg, k0n, tid);
            CP_COMMIT();
            if (tid < 64) rm = mask[b * SS_ + k0n + tid];
            CP_WAIT(1);
        } else {
            CP_WAIT(0);
        }
        __syncthreads();   // cur K/V + cur mask visible to all warps

        const uint32_t* Ks = sm + AT_KOFF + cur * 64 * AKS;
        const uint32_t* Vs = sm + AT_VOFF + cur * 64 * AVS;
        const float*   msk = (const float*)(sm + AT_MOFF + cur * 64);

        // S = Q @ K^T  (per-warp 16 x 64)
        float s[8][4];
#pragma unroll
        for (int nt = 0; nt < 8; nt++)
#pragma unroll
            for (int j = 0; j < 4; j++) s[nt][j] = 0.0f;

#pragma unroll
        for (int ks = 0; ks < 64; ks += 8) {
            uint32_t a[4];
            a[0] = Qs[(wq + g) * AQS + ks + q];
            a[1] = Qs[(wq + g + 8) * AQS + ks + q];
            a[2] = Qs[(wq + g) * AQS + ks + q + 4];
            a[3] = Qs[(wq + g + 8) * AQS + ks + q + 4];
#pragma unroll
            for (int nt = 0; nt < 8; nt++) {
                uint32_t bb[2];
                bb[0] = s2tf32(Ks[(nt * 8 + g) * AKS + ks + q]);
                bb[1] = s2tf32(Ks[(nt * 8 + g) * AKS + ks + q + 4]);
                mma_tf32(s[nt], a, bb);
            }
        }

        // Mask + row max (rows g and g+8; this warp owns the full 64-key width)
        float mx0 = -1e30f, mx1 = -1e30f;
#pragma unroll
        for (int nt = 0; nt < 8; nt++) {
            int col = nt * 8 + 2 * q;
            float mk0 = 1.0e6f * (1.0f - msk[col]);
            float mk1 = 1.0e6f * (1.0f - msk[col + 1]);
            s[nt][0] -= mk0; s[nt][1] -= mk1;
            s[nt][2] -= mk0; s[nt][3] -= mk1;
            mx0 = fmaxf(mx0, fmaxf(s[nt][0], s[nt][1]));
            mx1 = fmaxf(mx1, fmaxf(s[nt][2], s[nt][3]));
        }
        mx0 = fmaxf(mx0, __shfl_xor_sync(0xffffffffu, mx0, 1));
        mx0 = fmaxf(mx0, __shfl_xor_sync(0xffffffffu, mx0, 2));
        mx1 = fmaxf(mx1, __shfl_xor_sync(0xffffffffu, mx1, 1));
        mx1 = fmaxf(mx1, __shfl_xor_sync(0xffffffffu, mx1, 2));

        float mn0 = fmaxf(m0r, mx0), mn1 = fmaxf(m1r, mx1);
        float c0 = __expf(m0r - mn0), c1 = __expf(m1r - mn1);
        m0r = mn0; m1r = mn1;

        float s0 = 0.0f, s1 = 0.0f;
#pragma unroll
        for (int nt = 0; nt < 8; nt++) {
            float p0 = __expf(s[nt][0] - mn0);
            float p1 = __expf(s[nt][1] - mn0);
            float p2 = __expf(s[nt][2] - mn1);
            float p3 = __expf(s[nt][3] - mn1);
            s0 += p0 + p1; s1 += p2 + p3;
            int col = nt * 8 + 2 * q;
            Ps[(wq + g) * APS + col]     = f2tf32(p0);
            Ps[(wq + g) * APS + col + 1] = f2tf32(p1);
            Ps[(wq + g + 8) * APS + col]     = f2tf32(p2);
            Ps[(wq + g + 8) * APS + col + 1] = f2tf32(p3);
            O[nt][0] *= c0; O[nt][1] *= c0;
            O[nt][2] *= c1; O[nt][3] *= c1;
        }
        s0 += __shfl_xor_sync(0xffffffffu, s0, 1);
        s0 += __shfl_xor_sync(0xffffffffu, s0, 2);
        s1 += __shfl_xor_sync(0xffffffffu, s1, 1);
        s1 += __shfl_xor_sync(0xffffffffu, s1, 2);
        l0 = l0 * c0 + s0;
        l1 = l1 * c1 + s1;

        __syncwarp();   // Ps rows [wq, wq+16) are warp-private; lane visibility only

        // O += P @ V  (k = key dim 64)
#pragma unroll
        for (int ks = 0; ks < 64; ks += 8) {
            uint32_t a[4];
            a[0] = Ps[(wq + g) * APS + ks + q];
            a[1] = Ps[(wq + g + 8) * APS + ks + q];
            a[2] = Ps[(wq + g) * APS + ks + q + 4];
            a[3] = Ps[(wq + g + 8) * APS + ks + q + 4];
#pragma unroll
            for (int nt = 0; nt < 8; nt++) {
                uint32_t bb[2];
                bb[0] = s2tf32(Vs[(ks + q) * AVS + nt * 8 + g]);
                bb[1] = s2tf32(Vs[(ks + q + 4) * AVS + nt * 8 + g]);
                mma_tf32(O[nt], a, bb);
            }
        }

        // Stage next mask into the alternate slot (read next iter after sync)
        if (kt + 1 < SS_ / 64 && tid < 64)
            ((float*)(sm + AT_MOFF + nxt * 64))[tid] = rm;
        __syncthreads();   // cur K/V rewritten by next iteration's cp.async
    }

    // Normalize and write ctx [B,S,H*DH]
    float inv0 = 1.0f / l0, inv1 = 1.0f / l1;
    int qr0 = q0 + wq + g;
    int qr1 = qr0 + 8;
#pragma unroll
    for (int nt = 0; nt < 8; nt++) {
        int d = nt * 8 + 2 * q;
        float2 v0 = make_float2(O[nt][0] * inv0, O[nt][1] * inv0);
        float2 v1 = make_float2(O[nt][2] * inv1, O[nt][3] * inv1);
        *(float2*)(g_C + ((size_t)(b * SS_ + qr0)) * HD_ + h * 64 + d) = v0;
        *(float2*)(g_C + ((size_t)(b * SS_ + qr1)) * HD_ + h * 64 + d) = v1;
    }
}

// ===========================================================================
extern "C" void kernel_launch(void* const* d_in, const int* in_sizes, int n_in,
                              void* d_out, int out_size)
{
    const float* X    = (const float*)d_in[0];
    const float* mask = (const float*)d_in[1];
    const float* Wq   = (const float*)d_in[2];
    const float* bq   = (const float*)d_in[3];
    const float* Wk   = (const float*)d_in[4];
    const float* bk   = (const float*)d_in[5];
    const float* Wv   = (const float*)d_in[6];
    const float* bv   = (const float*)d_in[7];
    const float* Wo   = (const float*)d_in[8];
    const float* bo   = (const float*)d_in[9];
    float* out        = (float*)d_out;

    cudaFuncSetAttribute(gemm_mma<0>, cudaFuncAttributeMaxDynamicSharedMemorySize,
                         GEMM_SMEM_BYTES);
    cudaFuncSetAttribute(gemm_mma<1>, cudaFuncAttributeMaxDynamicSharedMemorySize,
                         GEMM_SMEM_BYTES);
    cudaFuncSetAttribute(attn_mma, cudaFuncAttributeMaxDynamicSharedMemorySize,
                         ATTN_SMEM_BYTES);

    gemm_mma<0><<<dim3(HD_ / 128, MM / 128, 3), 256, GEMM_SMEM_BYTES>>>(
        X, Wq, bq, Wk, bk, Wv, bv, nullptr);
    attn_mma<<<dim3(SS_ / 128, BB * HH), 256, ATTN_SMEM_BYTES>>>(mask);
    // MODE 1 reads W=W0, bias=b0 — Wo/bo go in those slots.
    gemm_mma<1><<<dim3(DIM_ / 128, MM / 128), 256, GEMM_SMEM_BYTES>>>(
        nullptr, Wo, bo, nullptr, nullptr, nullptr, nullptr, out);
}

// round 15
// speedup vs baseline: 1.9852x; 1.0004x over previous
#include <cuda_runtime.h>
#include <cuda_fp16.h>
#include <cstdint>

// Problem constants
#define BB   2
#define SS_  2048
#define DIM_ 1024
#define HH   16
#define DH_  64
#define MM   (BB * SS_)     // 4096
#define HD_  (HH * DH_)     // 1024

// Scratch (device globals: allocation-free rule)
__device__ float g_Q[BB * HH * SS_ * DH_];   // [B,H,S,DH]
__device__ float g_K[BB * HH * SS_ * DH_];
__device__ float g_V[BB * HH * SS_ * DH_];
__device__ float g_C[MM * HD_];              // ctx, [B,S,H*DH] row-major

// ---------------------------------------------------------------------------
// Helpers
// ---------------------------------------------------------------------------
__device__ __forceinline__ uint32_t smem_u32(const void* p) {
    uint32_t a;
    asm("{ .reg .u64 t; cvta.to.shared.u64 t, %1; cvt.u32.u64 %0, t; }"
        : "=r"(a) : "l"(p));
    return a;
}

__device__ __forceinline__ uint32_t f2tf32(float x) {
    uint32_t u;
    asm("cvt.rna.tf32.f32 %0, %1;" : "=r"(u) : "f"(x));
    return u;
}

__device__ __forceinline__ uint32_t s2tf32(uint32_t raw) {
    return f2tf32(__uint_as_float(raw));
}

__device__ __forceinline__ uint32_t packh2(float lo, float hi) {
    __half2 h = __floats2half2_rn(lo, hi);
    return *(uint32_t*)&h;
}

__device__ __forceinline__ void cp_async16(uint32_t saddr, const void* gptr) {
    asm volatile("cp.async.cg.shared.global [%0], [%1], 16;"
                 :: "r"(saddr), "l"(gptr));
}
#define CP_COMMIT() asm volatile("cp.async.commit_group;" ::: "memory")
#define CP_WAIT(n)  asm volatile("cp.async.wait_group %0;" :: "n"(n) : "memory")

// D = A(16x8 tf32) * B(8x8 tf32) + D, fp32 accumulate
__device__ __forceinline__ void mma_tf32(float* c, const uint32_t* a, const uint32_t* b) {
    asm volatile(
        "mma.sync.aligned.m16n8k8.row.col.f32.tf32.tf32.f32 "
        "{%0,%1,%2,%3}, {%4,%5,%6,%7}, {%8,%9}, {%0,%1,%2,%3};"
        : "+f"(c[0]), "+f"(c[1]), "+f"(c[2]), "+f"(c[3])
        : "r"(a[0]), "r"(a[1]), "r"(a[2]), "r"(a[3]), "r"(b[0]), "r"(b[1]));
}

// D = A(16x16 f16) * B(16x8 f16) + D, fp32 accumulate
__device__ __forceinline__ void mma_f16(float* c, const uint32_t* a, const uint32_t* b) {
    asm volatile(
        "mma.sync.aligned.m16n8k16.row.col.f32.f16.f16.f32 "
        "{%0,%1,%2,%3}, {%4,%5,%6,%7}, {%8,%9}, {%0,%1,%2,%3};"
        : "+f"(c[0]), "+f"(c[1]), "+f"(c[2]), "+f"(c[3])
        : "r"(a[0]), "r"(a[1]), "r"(a[2]), "r"(a[3]), "r"(b[0]), "r"(b[1]));
}

// ===========================================================================
// tf32 mma.sync GEMM, cp.async double-buffered — UNCHANGED from R13 (proven)
// ===========================================================================
#define GAS 36    // As stride (u32)
#define GBS 132   // Bs stride (u32)
#define GEMM_ABUF (128 * GAS)             // 4608 u32
#define GEMM_BBUF (32 * GBS)              // 4224 u32
#define GEMM_SMEM_U32 (2 * (GEMM_ABUF + GEMM_BBUF))
#define GEMM_SMEM_BYTES (GEMM_SMEM_U32 * 4)   // 70656
#define NCH (DIM_ / 32)                   // 32 k-chunks

__device__ __forceinline__ void gemm_cp(uint32_t a_s, uint32_t b_s,
                                        const float* __restrict__ A,
                                        const float* __restrict__ W,
                                        int m0, int n0, int k0, int tid) {
#pragma unroll
    for (int t = 0; t < 4; t++) {
        int idx = tid + t * 256;
        int r = idx >> 3;
        int c4 = (idx & 7) << 2;
        cp_async16(a_s + (uint32_t)(r * GAS + c4) * 4,
                   A + (size_t)(m0 + r) * DIM_ + k0 + c4);
    }
#pragma unroll
    for (int t = 0; t < 4; t++) {
        int idx = tid + t * 256;
        int kk = idx >> 5;
        int n4 = (idx & 31) << 2;
        cp_async16(b_s + (uint32_t)(kk * GBS + n4) * 4,
                   W + (size_t)(k0 + kk) * HD_ + n0 + n4);
    }
}

template <int MODE>
__global__ __launch_bounds__(256) void gemm_mma(
    const float* __restrict__ Ain,
    const float* __restrict__ W0, const float* __restrict__ b0,
    const float* __restrict__ W1, const float* __restrict__ b1,
    const float* __restrict__ W2, const float* __restrict__ b2,
    float* __restrict__ outp)
{
    extern __shared__ uint32_t dsm[];
    const uint32_t sb = smem_u32(dsm);

    const int tid  = threadIdx.x;
    const int wid  = tid >> 5;
    const int lane = tid & 31;
    const int g    = lane >> 2;
    const int q    = lane & 3;
    const int m0 = blockIdx.y * 128;
    const int n0 = blockIdx.x * 128;
    const int wm = (wid >> 2) * 64;
    const int wn = (wid & 3) * 32;

    const float* A;
    const float* W;
    const float* bias;
    float* op;
    if (MODE == 0) {
        A = Ain;
        int z = blockIdx.z;
        W    = (z == 0) ? W0 : (z == 1) ? W1 : W2;
        bias = (z == 0) ? b0 : (z == 1) ? b1 : b2;
        op   = nullptr;
    } else {
        A = g_C; W = W0; bias = b0; op = outp;
    }

    float acc[4][4][4];
#pragma unroll
    for (int mt = 0; mt < 4; mt++)
#pragma unroll
        for (int nt = 0; nt < 4; nt++)
#pragma unroll
            for (int j = 0; j < 4; j++) acc[mt][nt][j] = 0.0f;

    gemm_cp(sb, sb + 2 * GEMM_ABUF * 4, A, W, m0, n0, 0, tid);
    CP_COMMIT();

#pragma unroll 1
    for (int c = 0; c < NCH; c++) {
        const int cur = c & 1;
        if (c + 1 < NCH) {
            const int nxt = cur ^ 1;
            gemm_cp(sb + nxt * GEMM_ABUF * 4,
                    sb + (2 * GEMM_ABUF + nxt * GEMM_BBUF) * 4,
                    A, W, m0, n0, (c + 1) * 32, tid);
            CP_COMMIT();
            CP_WAIT(1);
        } else {
            CP_WAIT(0);
        }
        __syncthreads();

        const uint32_t* As = dsm + cur * GEMM_ABUF;
        const uint32_t* Bs = dsm + 2 * GEMM_ABUF + cur * GEMM_BBUF;
#pragma unroll
        for (int ks = 0; ks < 32; ks += 8) {
            uint32_t a[4][4], bfr[4][2];
#pragma unroll
            for (int mt = 0; mt < 4; mt++) {
                int r = wm + mt * 16 + g;
                a[mt][0] = s2tf32(As[r * GAS + ks + q]);
                a[mt][1] = s2tf32(As[(r + 8) * GAS + ks + q]);
                a[mt][2] = s2tf32(As[r * GAS + ks + q + 4]);
                a[mt][3] = s2tf32(As[(r + 8) * GAS + ks + q + 4]);
            }
#pragma unroll
            for (int nt = 0; nt < 4; nt++) {
                int n = wn + nt * 8 + g;
                bfr[nt][0] = s2tf32(Bs[(ks + q) * GBS + n]);
                bfr[nt][1] = s2tf32(Bs[(ks + q + 4) * GBS + n]);
            }
#pragma unroll
            for (int mt = 0; mt < 4; mt++)
#pragma unroll
                for (int nt = 0; nt < 4; nt++)
                    mma_tf32(acc[mt][nt], a[mt], bfr[nt]);
        }
        __syncthreads();
    }

#pragma unroll
    for (int mt = 0; mt < 4; mt++) {
#pragma unroll
        for (int nt = 0; nt < 4; nt++) {
            int n = n0 + wn + nt * 8 + 2 * q;
            float bn0 = bias[n], bn1 = bias[n + 1];
            int mA = m0 + wm + mt * 16 + g;
            int mB = mA + 8;
            float2 v0 = make_float2(acc[mt][nt][0] + bn0, acc[mt][nt][1] + bn1);
            float2 v1 = make_float2(acc[mt][nt][2] + bn0, acc[mt][nt][3] + bn1);
            if (MODE == 0) {
                float* dst = (blockIdx.z == 0) ? g_Q : (blockIdx.z == 1) ? g_K : g_V;
                int h = n >> 6, d = n & 63;
                int bA = mA >> 11, sA = mA & 2047;
                int bW = mB >> 11, sB = mB & 2047;
                *(float2*)(dst + ((((size_t)(bA * HH + h)) * SS_ + sA) << 6) + d) = v0;
                *(float2*)(dst + ((((size_t)(bW * HH + h)) * SS_ + sB) << 6) + d) = v1;
            } else {
                *(float2*)(op + (size_t)mA * DIM_ + n) = v0;
                *(float2*)(op + (size_t)mB * DIM_ + n) = v1;
            }
        }
    }
}

// ===========================================================================
// Flash attention, fp16 mma.sync m16n8k16
//   q-tile 128 per CTA, 8 warps x 16 q-rows, key-tile 64, DH=64.
//   Q/K packed half2 along d; V packed half2 across key pairs.
//   P lives in registers (S-frag cols 2q,2q+1 pack directly into PV A-frag).
// ===========================================================================
#define QW 36     // Qs word stride (half2 words per row + pad)
#define KW 36
#define VW 72
#define AQ_OFF 0
#define AK_OFF (128 * QW)              // 4608
#define AV_OFF (AK_OFF + 64 * KW)      // 6912
#define AM_OFF (AV_OFF + 32 * VW)      // 9216
#define ATTN_SMEM_U32 (AM_OFF + 64)
#define ATTN_SMEM_BYTES (ATTN_SMEM_U32 * 4)   // 37120

__global__ __launch_bounds__(256) void attn_f16(const float* __restrict__ mask)
{
    extern __shared__ uint32_t sm[];
    uint32_t* Qs = sm + AQ_OFF;
    uint32_t* Ks = sm + AK_OFF;
    uint32_t* Vs = sm + AV_OFF;
    float*   msk = (float*)(sm + AM_OFF);

    const int tid  = threadIdx.x;
    const int wid  = tid >> 5;
    const int lane = tid & 31;
    const int g    = lane >> 2;
    const int q    = lane & 3;
    const int bh = blockIdx.y;
    const int b  = bh >> 4;
    const int h  = bh & 15;
    const int q0 = blockIdx.x * 128;
    const int wq = wid * 16;

    const float* Qg = g_Q + (size_t)bh * SS_ * DH_;
    const float* Kg = g_K + (size_t)bh * SS_ * DH_;
    const float* Vg = g_V + (size_t)bh * SS_ * DH_;

    // Load Q tile (128 x 64), fold 1/sqrt(DH)=0.125, pack half2 along d
#pragma unroll
    for (int t = 0; t < 8; t++) {
        int idx = tid + t * 256;
        int r = idx >> 4;
        int c4 = (idx & 15) * 4;
        float4 v = *(const float4*)(Qg + (size_t)(q0 + r) * DH_ + c4);
        Qs[r * QW + (c4 >> 1)]     = packh2(v.x * 0.125f, v.y * 0.125f);
        Qs[r * QW + (c4 >> 1) + 1] = packh2(v.z * 0.125f, v.w * 0.125f);
    }

    float O[8][4];
#pragma unroll
    for (int nt = 0; nt < 8; nt++)
#pragma unroll
        for (int j = 0; j < 4; j++) O[nt][j] = 0.0f;
    float m0r = -1e30f, m1r = -1e30f, l0 = 0.0f, l1 = 0.0f;

#pragma unroll 1
    for (int kt = 0; kt < SS_ / 64; kt++) {
        const int k0 = kt * 64;
        __syncthreads();   // protect Ks/Vs (prev tile consumers done)

        // K: 64 keys x 64 d, packed half2 along d
#pragma unroll
        for (int t = 0; t < 4; t++) {
            int idx = tid + t * 256;
            int r = idx >> 4;
            int c4 = (idx & 15) * 4;
            float4 kv = *(const float4*)(Kg + (size_t)(k0 + r) * DH_ + c4);
            Ks[r * KW + (c4 >> 1)]     = packh2(kv.x, kv.y);
            Ks[r * KW + (c4 >> 1) + 1] = packh2(kv.z, kv.w);
        }
        // V: packed half2 across key pairs: word(kp, d) = {V[2kp][d], V[2kp+1][d]}
#pragma unroll
        for (int t = 0; t < 2; t++) {
            int idx = tid + t * 256;
            int kp = idx >> 4;          // 0..31
            int d4 = (idx & 15) * 4;
            float4 va = *(const float4*)(Vg + (size_t)(k0 + 2 * kp) * DH_ + d4);
            float4 vb = *(const float4*)(Vg + (size_t)(k0 + 2 * kp + 1) * DH_ + d4);
            uint32_t* pv = &Vs[kp * VW + d4];
            pv[0] = packh2(va.x, vb.x);
            pv[1] = packh2(va.y, vb.y);
            pv[2] = packh2(va.z, vb.z);
            pv[3] = packh2(va.w, vb.w);
        }
        if (tid < 64) msk[tid] = mask[b * SS_ + k0 + tid];
        __syncthreads();

        // S = Q @ K^T  (per-warp 16 x 64), 4 k16 steps over d
        float s[8][4];
#pragma unroll
        for (int nt = 0; nt < 8; nt++)
#pragma unroll
            for (int j = 0; j < 4; j++) s[nt][j] = 0.0f;

#pragma unroll
        for (int st = 0; st < 4; st++) {
            uint32_t a[4];
            a[0] = Qs[(wq + g) * QW + 8 * st + q];
            a[1] = Qs[(wq + g + 8) * QW + 8 * st + q];
            a[2] = Qs[(wq + g) * QW + 8 * st + q + 4];
            a[3] = Qs[(wq + g + 8) * QW + 8 * st + q + 4];
#pragma unroll
            for (int nt = 0; nt < 8; nt++) {
                uint32_t bb[2];
                bb[0] = Ks[(nt * 8 + g) * KW + 8 * st + q];
                bb[1] = Ks[(nt * 8 + g) * KW + 8 * st + q + 4];
                mma_f16(s[nt], a, bb);
            }
        }

        // Mask + row max (rows g, g+8; warp owns all 64 keys)
        float mx0 = -1e30f, mx1 = -1e30f;
#pragma unroll
        for (int nt = 0; nt < 8; nt++) {
            int col = nt * 8 + 2 * q;
            float mk0 = 1.0e6f * (1.0f - msk[col]);
            float mk1 = 1.0e6f * (1.0f - msk[col + 1]);
            s[nt][0] -= mk0; s[nt][1] -= mk1;
            s[nt][2] -= mk0; s[nt][3] -= mk1;
            mx0 = fmaxf(mx0, fmaxf(s[nt][0], s[nt][1]));
            mx1 = fmaxf(mx1, fmaxf(s[nt][2], s[nt][3]));
        }
        mx0 = fmaxf(mx0, __shfl_xor_sync(0xffffffffu, mx0, 1));
        mx0 = fmaxf(mx0, __shfl_xor_sync(0xffffffffu, mx0, 2));
        mx1 = fmaxf(mx1, __shfl_xor_sync(0xffffffffu, mx1, 1));
        mx1 = fmaxf(mx1, __shfl_xor_sync(0xffffffffu, mx1, 2));

        float mn0 = fmaxf(m0r, mx0), mn1 = fmaxf(m1r, mx1);
        float c0 = __expf(m0r - mn0), c1 = __expf(m1r - mn1);
        m0r = mn0; m1r = mn1;

        // exp + pack P into PV A-fragments (registers only, no SMEM)
        uint32_t ph[8][2];
        float s0 = 0.0f, s1 = 0.0f;
#pragma unroll
        for (int nt = 0; nt < 8; nt++) {
            float p0 = __expf(s[nt][0] - mn0);
            float p1 = __expf(s[nt][1] - mn0);
            float p2 = __expf(s[nt][2] - mn1);
            float p3 = __expf(s[nt][3] - mn1);
            s0 += p0 + p1; s1 += p2 + p3;
            ph[nt][0] = packh2(p0, p1);     // rows g   : cols 2q, 2q+1
            ph[nt][1] = packh2(p2, p3);     // rows g+8 : cols 2q, 2q+1
            O[nt][0] *= c0; O[nt][1] *= c0;
            O[nt][2] *= c1; O[nt][3] *= c1;
        }
        s0 += __shfl_xor_sync(0xffffffffu, s0, 1);
        s0 += __shfl_xor_sync(0xffffffffu, s0, 2);
        s1 += __shfl_xor_sync(0xffffffffu, s1, 1);
        s1 += __shfl_xor_sync(0xffffffffu, s1, 2);
        l0 = l0 * c0 + s0;
        l1 = l1 * c1 + s1;

        // O += P @ V : A from ph regs, B from packed Vs. 4 k16 steps over keys.
#pragma unroll
        for (int j = 0; j < 4; j++) {
            uint32_t a[4];
            a[0] = ph[2 * j][0];       // rows g   , keys 16j+2q,+1
            a[1] = ph[2 * j][1];       // rows g+8 , keys 16j+2q,+1
            a[2] = ph[2 * j + 1][0];   // rows g   , keys 16j+8+2q,+1
            a[3] = ph[2 * j + 1][1];   // rows g+8 , keys 16j+8+2q,+1
#pragma unroll
            for (int nt = 0; nt < 8; nt++) {
                uint32_t bb[2];
                bb[0] = Vs[(8 * j + q) * VW + nt * 8 + g];
                bb[1] = Vs[(8 * j + q + 4) * VW + nt * 8 + g];
                mma_f16(O[nt], a, bb);
            }
        }
    }

    // Normalize and write ctx [B,S,H*DH]
    float inv0 = 1.0f / l0, inv1 = 1.0f / l1;
    int qr0 = q0 + wq + g;
    int qr1 = qr0 + 8;
#pragma unroll
    for (int nt = 0; nt < 8; nt++) {
        int d = nt * 8 + 2 * q;
        float2 v0 = make_float2(O[nt][0] * inv0, O[nt][1] * inv0);
        float2 v1 = make_float2(O[nt][2] * inv1, O[nt][3] * inv1);
        *(float2*)(g_C + ((size_t)(b * SS_ + qr0)) * HD_ + h * 64 + d) = v0;
        *(float2*)(g_C + ((size_t)(b * SS_ + qr1)) * HD_ + h * 64 + d) = v1;
    }
}

// ===========================================================================
extern "C" void kernel_launch(void* const* d_in, const int* in_sizes, int n_in,
                              void* d_out, int out_size)
{
    const float* X    = (const float*)d_in[0];
    const float* mask = (const float*)d_in[1];
    const float* Wq   = (const float*)d_in[2];
    const float* bq   = (const float*)d_in[3];
    const float* Wk   = (const float*)d_in[4];
    const float* bk   = (const float*)d_in[5];
    const float* Wv   = (const float*)d_in[6];
    const float* bv   = (const float*)d_in[7];
    const float* Wo   = (const float*)d_in[8];
    const float* bo   = (const float*)d_in[9];
    float* out        = (float*)d_out;

    cudaFuncSetAttribute(gemm_mma<0>, cudaFuncAttributeMaxDynamicSharedMemorySize,
                         GEMM_SMEM_BYTES);
    cudaFuncSetAttribute(gemm_mma<1>, cudaFuncAttributeMaxDynamicSharedMemorySize,
                         GEMM_SMEM_BYTES);
    cudaFuncSetAttribute(attn_f16, cudaFuncAttributeMaxDynamicSharedMemorySize,
                         ATTN_SMEM_BYTES);

    gemm_mma<0><<<dim3(HD_ / 128, MM / 128, 3), 256, GEMM_SMEM_BYTES>>>(
        X, Wq, bq, Wk, bk, Wv, bv, nullptr);
    attn_f16<<<dim3(SS_ / 128, BB * HH), 256, ATTN_SMEM_BYTES>>>(mask);
    // MODE 1 reads W=W0, bias=b0 — Wo/bo go in those slots.
    gemm_mma<1><<<dim3(DIM_ / 128, MM / 128), 256, GEMM_SMEM_BYTES>>>(
        nullptr, Wo, bo, nullptr, nullptr, nullptr, nullptr, out);
}